// round 15
// baseline (speedup 1.0000x reference)
#include <cuda_runtime.h>
#include <cuda_fp16.h>
#include <cstdint>

#define BS    32
#define NROW  2048
#define MCOL  512
#define ITERS 200
#define INV_EPS 10.0f
#define CPB   4                          // CTAs per batch (128 CTAs <= 148 SMs: all resident)
#define TPB   512                        // 16 warps
#define NWARP (TPB / 32)                 // 16
#define NSLOT (NWARP / 2)                // 8 swred slots (two-phase fold)
#define ROWS_PER_CTA  (NROW / CPB)       // 512
#define ROWS_PER_WARP (ROWS_PER_CTA / NWARP)  // 32
#define RELT  128                        // threads that store partials + release
#define RESROWS 12                       // L1-resident rows/warp (192KB/CTA <= ~208KB carveout)
#define CONV_TOL 1e-5f                   // relative v-delta for early exit

// Scratch (__device__ globals per allocation-free rule; zero-initialized at load).
__device__ __half2       g_G[(size_t)BS * NROW * (MCOL / 2)];  // 64 MB, L2-resident
__device__ float         g_u[BS * NROW];
__device__ float         g_part[2][BS][CPB][MCOL];             // double-buffered CTA partials
__device__ unsigned int  g_bar[BS];                            // per-batch barrier counters
__device__ unsigned int  g_done;                               // last-CTA-out counter

// Packed fp32x2 FMA.
__device__ __forceinline__ void ffma2(float2& d, const float2 a, const float2 b) {
    unsigned long long da = *(const unsigned long long*)&a;
    unsigned long long db = *(const unsigned long long*)&b;
    unsigned long long dd = *(unsigned long long*)&d;
    asm("fma.rn.f32x2 %0, %1, %2, %3;" : "=l"(dd) : "l"(da), "l"(db), "l"(dd));
    d = *(float2*)&dd;
}

__device__ __forceinline__ float2 h2lo(unsigned int h) {
    return __half22float2(*(const __half2*)&h);
}
__device__ __forceinline__ unsigned int f22h2(float x, float y) {
    __half2 h = __floats2half2_rn(x, y);
    return *(unsigned int*)&h;
}

// Row core: dot(G_row, v) -> warp-reduce -> u -> colacc += u * G_row.
__device__ __forceinline__ void row_core(const float2 gf[8],
                                         const float2* __restrict__ vreg,
                                         float2* __restrict__ colacc,
                                         float mu_r, float* uout, int lane) {
    float2 acc = make_float2(0.f, 0.f);
#pragma unroll
    for (int k = 0; k < 8; k++) ffma2(acc, gf[k], vreg[k]);
    float s = acc.x + acc.y;
#pragma unroll
    for (int off = 16; off; off >>= 1)
        s += __shfl_xor_sync(0xffffffffu, s, off);
    float u = __fdividef(mu_r, s);
    if (lane == 0) *uout = u;          // re-read in the fused epilogue
    float2 u2 = make_float2(u, u);
#pragma unroll
    for (int k = 0; k < 8; k++) ffma2(colacc[k], gf[k], u2);
}

// ---------------------------------------------------------------------------
// Single persistent kernel:
//   iter 0    : G = exp(-C/eps) fp16 generated inline (v0 = 1/m const), C read
//               exactly once via __ldcg.
//   iters 1+  : one fp16-G pass/iter, 4-row load batching, first RESROWS rows
//               L1-resident (no fences anywhere -> L1 never flushed).
//   exit      : deterministic per-batch convergence test on v.
//   epilogue  : P = u * G * v written straight from L2-hot G + smem v;
//               last CTA out resets barrier state for the next graph replay.
// ---------------------------------------------------------------------------
__global__ void __launch_bounds__(TPB, 1)
sink_iter(const float* __restrict__ C, const float* __restrict__ mu,
          const float* __restrict__ nu, float* __restrict__ P) {
    const int cta  = blockIdx.x;
    const int b    = cta / CPB;
    const int r    = cta % CPB;
    const int tid  = threadIdx.x;
    const int lane = tid & 31;
    const int w    = tid >> 5;

    __shared__ __align__(16) float sv[MCOL];            // v for this batch
    __shared__ float smu[ROWS_PER_CTA];                 // mu slice for this CTA
    __shared__ __align__(16) float swred[NSLOT][MCOL];  // folded warp partials (16KB)
    __shared__ float sdel[RELT / 32];                   // per-warp max |dv|/v
    __shared__ int   sbrk;

    const int rowbase = r * ROWS_PER_CTA;
    for (int j = tid; j < MCOL; j += TPB) sv[j] = 1.0f / MCOL;
    for (int j = tid; j < ROWS_PER_CTA; j += TPB) smu[j] = mu[rowbase + j];
    if (tid == 0) sbrk = 0;
    __syncthreads();

    const int i0 = rowbase + w * ROWS_PER_WARP;
    uint4*        Gw  = (uint4*)(g_G + ((size_t)b * NROW + i0) * (MCOL / 2));
    const float*  Cw  = C + ((size_t)b * NROW + i0) * MCOL;
    float*        uw  = g_u + b * NROW + i0;
    const float2* sv2 = (const float2*)sv;
    unsigned int* bar = &g_bar[b];
    const int h0 = 4 * lane;          // half2 group 1: cols 8l..8l+7
    const int h1 = 128 + 4 * lane;    // half2 group 2: cols 256+8l..+7

    for (int t = 0; t < ITERS; t++) {
        float2 vreg[8];
#pragma unroll
        for (int k = 0; k < 4; k++) { vreg[k] = sv2[h0 + k]; vreg[4 + k] = sv2[h1 + k]; }

        float2 colacc[8];
#pragma unroll
        for (int k = 0; k < 8; k++) colacc[k] = make_float2(0.f, 0.f);

        if (t == 0) {
            // Fused init: C -> G fp16 (written once) + iteration 0 on the
            // quantized values. __ldcg keeps C out of L1 (reserved for G).
#pragma unroll 2
            for (int rr = 0; rr < ROWS_PER_WARP; rr++) {
                const float4* cp = (const float4*)(Cw + (size_t)rr * MCOL);
                float4 a0 = __ldcg(cp + 2 * lane),      a1 = __ldcg(cp + 2 * lane + 1);
                float4 b0 = __ldcg(cp + 64 + 2 * lane), b1 = __ldcg(cp + 64 + 2 * lane + 1);
                uint4 q0, q1;
                q0.x = f22h2(__expf(-a0.x * INV_EPS), __expf(-a0.y * INV_EPS));
                q0.y = f22h2(__expf(-a0.z * INV_EPS), __expf(-a0.w * INV_EPS));
                q0.z = f22h2(__expf(-a1.x * INV_EPS), __expf(-a1.y * INV_EPS));
                q0.w = f22h2(__expf(-a1.z * INV_EPS), __expf(-a1.w * INV_EPS));
                q1.x = f22h2(__expf(-b0.x * INV_EPS), __expf(-b0.y * INV_EPS));
                q1.y = f22h2(__expf(-b0.z * INV_EPS), __expf(-b0.w * INV_EPS));
                q1.z = f22h2(__expf(-b1.x * INV_EPS), __expf(-b1.y * INV_EPS));
                q1.w = f22h2(__expf(-b1.z * INV_EPS), __expf(-b1.w * INV_EPS));
                uint4* rp = Gw + rr * (MCOL / 8);
                rp[lane]      = q0;
                rp[32 + lane] = q1;
                float2 gf[8];
                gf[0] = h2lo(q0.x); gf[1] = h2lo(q0.y); gf[2] = h2lo(q0.z); gf[3] = h2lo(q0.w);
                gf[4] = h2lo(q1.x); gf[5] = h2lo(q1.y); gf[6] = h2lo(q1.z); gf[7] = h2lo(q1.w);
                row_core(gf, vreg, colacc, smu[w * ROWS_PER_WARP + rr], uw + rr, lane);
            }
        } else {
#pragma unroll
            for (int chunk = 0; chunk < ROWS_PER_WARP / 4; chunk++) {
                uint4 Pq[4][2];
#pragma unroll
                for (int q = 0; q < 4; q++) {
                    const int rr = chunk * 4 + q;
                    const uint4* rp = Gw + rr * (MCOL / 8);
                    if (rr < RESROWS) {                 // L1-resident subset
                        Pq[q][0] = rp[lane];
                        Pq[q][1] = rp[32 + lane];
                    } else {                            // streaming: L2 only
                        Pq[q][0] = __ldcg(rp + lane);
                        Pq[q][1] = __ldcg(rp + 32 + lane);
                    }
                }
#pragma unroll
                for (int q = 0; q < 4; q++) {
                    const int rr = chunk * 4 + q;
                    float2 gf[8];
                    gf[0] = h2lo(Pq[q][0].x); gf[1] = h2lo(Pq[q][0].y);
                    gf[2] = h2lo(Pq[q][0].z); gf[3] = h2lo(Pq[q][0].w);
                    gf[4] = h2lo(Pq[q][1].x); gf[5] = h2lo(Pq[q][1].y);
                    gf[6] = h2lo(Pq[q][1].z); gf[7] = h2lo(Pq[q][1].w);
                    row_core(gf, vreg, colacc, smu[w * ROWS_PER_WARP + rr], uw + rr, lane);
                }
            }
        }

        // Phase 1: warps 0-7 store partials (STS.128, no atomics).
        if (w < NSLOT) {
            float4* d0 = (float4*)&swred[w][2 * h0];
            d0[0] = make_float4(colacc[0].x, colacc[0].y, colacc[1].x, colacc[1].y);
            d0[1] = make_float4(colacc[2].x, colacc[2].y, colacc[3].x, colacc[3].y);
            float4* d1 = (float4*)&swred[w][2 * h1];
            d1[0] = make_float4(colacc[4].x, colacc[4].y, colacc[5].x, colacc[5].y);
            d1[1] = make_float4(colacc[6].x, colacc[6].y, colacc[7].x, colacc[7].y);
        }
        __syncthreads();
        // Phase 2: warps 8-15 fold into slot w-8 (lane-disjoint RMW).
        if (w >= NSLOT) {
            const int ws = w - NSLOT;
            float4* d0 = (float4*)&swred[ws][2 * h0];
            float4 a0 = d0[0], a1 = d0[1];
            d0[0] = make_float4(a0.x + colacc[0].x, a0.y + colacc[0].y,
                                a0.z + colacc[1].x, a0.w + colacc[1].y);
            d0[1] = make_float4(a1.x + colacc[2].x, a1.y + colacc[2].y,
                                a1.z + colacc[3].x, a1.w + colacc[3].y);
            float4* d1 = (float4*)&swred[ws][2 * h1];
            float4 b0 = d1[0], b1 = d1[1];
            d1[0] = make_float4(b0.x + colacc[4].x, b0.y + colacc[4].y,
                                b0.z + colacc[5].x, b0.w + colacc[5].y);
            d1[1] = make_float4(b1.x + colacc[6].x, b1.y + colacc[6].y,
                                b1.z + colacc[7].x, b1.w + colacc[7].y);
        }
        __syncthreads();

        const int p = t & 1;
        if (tid < RELT) {
            float4 s = make_float4(0.f, 0.f, 0.f, 0.f);
#pragma unroll
            for (int w2 = 0; w2 < NSLOT; w2++) {
                float4 a = *(const float4*)&swred[w2][4 * tid];
                s.x += a.x; s.y += a.y; s.z += a.z; s.w += a.w;
            }
            ((float4*)&g_part[p][b][r][0])[tid] = s;
            // Release by the SAME thread that stored -> no membar/L1-flush.
            asm volatile("red.release.gpu.global.add.u32 [%0], %1;"
                         :: "l"(bar), "r"(1u) : "memory");
        }
        if (tid == 0) {
            const unsigned int target = (unsigned)(RELT * CPB) * (unsigned)(t + 1);
            unsigned int c;
            do {
                asm volatile("ld.acquire.gpu.global.u32 %0, [%1];"
                             : "=r"(c) : "l"(bar) : "memory");
                if (c >= target) break;
                __nanosleep(32);
            } while (true);
        }
        __syncthreads();

        // v update + convergence metric (bit-identical in all 4 CTAs).
        if (tid < RELT) {
            float4 cs = __ldcg((const float4*)&g_part[p][b][0][4 * tid]);
            float4 c1 = __ldcg((const float4*)&g_part[p][b][1][4 * tid]);
            float4 c2 = __ldcg((const float4*)&g_part[p][b][2][4 * tid]);
            float4 c3 = __ldcg((const float4*)&g_part[p][b][3][4 * tid]);
            cs.x += c1.x + c2.x + c3.x;  cs.y += c1.y + c2.y + c3.y;
            cs.z += c1.z + c2.z + c3.z;  cs.w += c1.w + c2.w + c3.w;
            float4 nu4 = __ldg((const float4*)&nu[4 * tid]);
            float4 vv;
            vv.x = nu4.x / cs.x;  vv.y = nu4.y / cs.y;
            vv.z = nu4.z / cs.z;  vv.w = nu4.w / cs.w;
            float4 old = ((float4*)sv)[tid];
            ((float4*)sv)[tid] = vv;
            float d = fmaxf(fmaxf(fabsf(vv.x - old.x) / vv.x,
                                  fabsf(vv.y - old.y) / vv.y),
                            fmaxf(fabsf(vv.z - old.z) / vv.z,
                                  fabsf(vv.w - old.w) / vv.w));
#pragma unroll
            for (int off = 16; off; off >>= 1)
                d = fmaxf(d, __shfl_xor_sync(0xffffffffu, d, off));
            if (lane == 0) sdel[w] = d;
        }
        __syncthreads();
        if (tid == 0) {
            float dm = fmaxf(fmaxf(sdel[0], sdel[1]), fmaxf(sdel[2], sdel[3]));
            sbrk = (t >= 2 && dm < CONV_TOL) ? 1 : 0;
        }
        __syncthreads();
        if (sbrk) break;    // identical decision in all CTAs of this batch
    }

    // ---- Fused epilogue: P = u * G * v (G fp16 from L2, v from smem) ----
    __syncthreads();        // g_u writes from last iteration visible block-wide
    {
        float2 vreg[8];
#pragma unroll
        for (int k = 0; k < 4; k++) { vreg[k] = sv2[h0 + k]; vreg[4 + k] = sv2[h1 + k]; }
        float* Prow = P + ((size_t)b * NROW + i0) * MCOL;
#pragma unroll 2
        for (int rr = 0; rr < ROWS_PER_WARP; rr++) {
            const uint4* rp = Gw + rr * (MCOL / 8);
            uint4 q0 = __ldcg(rp + lane);
            uint4 q1 = __ldcg(rp + 32 + lane);
            float u = uw[rr];                       // uniform broadcast load
            float2 gf[8];
            gf[0] = h2lo(q0.x); gf[1] = h2lo(q0.y); gf[2] = h2lo(q0.z); gf[3] = h2lo(q0.w);
            gf[4] = h2lo(q1.x); gf[5] = h2lo(q1.y); gf[6] = h2lo(q1.z); gf[7] = h2lo(q1.w);
            float4* dst0 = (float4*)(Prow + (size_t)rr * MCOL + 8 * lane);
            float4* dst1 = (float4*)(Prow + (size_t)rr * MCOL + 256 + 8 * lane);
            dst0[0] = make_float4(u * gf[0].x * vreg[0].x, u * gf[0].y * vreg[0].y,
                                  u * gf[1].x * vreg[1].x, u * gf[1].y * vreg[1].y);
            dst0[1] = make_float4(u * gf[2].x * vreg[2].x, u * gf[2].y * vreg[2].y,
                                  u * gf[3].x * vreg[3].x, u * gf[3].y * vreg[3].y);
            dst1[0] = make_float4(u * gf[4].x * vreg[4].x, u * gf[4].y * vreg[4].y,
                                  u * gf[5].x * vreg[5].x, u * gf[5].y * vreg[5].y);
            dst1[1] = make_float4(u * gf[6].x * vreg[6].x, u * gf[6].y * vreg[6].y,
                                  u * gf[7].x * vreg[7].x, u * gf[7].y * vreg[7].y);
        }
    }

    // ---- Last CTA out resets barrier state for the next graph replay ----
    __syncthreads();
    if (tid == 0) {
        unsigned int old = atomicAdd(&g_done, 1u);
        if (old == (unsigned)gridDim.x - 1u) {      // every other CTA fully done
#pragma unroll
            for (int i = 0; i < BS; i++) g_bar[i] = 0u;
            g_done = 0u;
        }
    }
}

// ---------------------------------------------------------------------------
extern "C" void kernel_launch(void* const* d_in, const int* in_sizes, int n_in,
                              void* d_out, int out_size) {
    const float* C  = (const float*)d_in[0];
    const float* mu = (const float*)d_in[1];
    const float* nu = (const float*)d_in[2];
    float*       P  = (float*)d_out;

    sink_iter<<<BS * CPB, TPB>>>(C, mu, nu, P);
}

// round 17
// speedup vs baseline: 1.0362x; 1.0362x over previous
#include <cuda_runtime.h>
#include <cuda_fp16.h>
#include <cstdint>

#define BS    32
#define NROW  2048
#define MCOL  512
#define ITERS 200
#define INV_EPS 10.0f
#define CPB   4                          // CTAs per batch (128 CTAs <= 148 SMs: all resident)
#define TPB   512                        // 16 warps
#define NWARP (TPB / 32)                 // 16
#define NSLOT (NWARP / 2)                // 8 swred slots (two-phase fold)
#define ROWS_PER_CTA  (NROW / CPB)       // 512
#define ROWS_PER_WARP (ROWS_PER_CTA / NWARP)  // 32
#define RELT  128                        // threads that store partials + release
#define RESROWS 12                       // L1-resident rows/warp (192KB/CTA <= ~208KB carveout)
#define CONV_TOL 1e-5f                   // relative v-delta for early exit

// Scratch (__device__ globals per allocation-free rule; zero-initialized at load).
__device__ __half2       g_G[(size_t)BS * NROW * (MCOL / 2)];  // 64 MB, L2-resident
__device__ float         g_u[BS * NROW];
__device__ float         g_v[BS * MCOL];
__device__ float         g_part[2][BS][CPB][MCOL];             // double-buffered CTA partials
__device__ unsigned int  g_bar[BS];                            // per-batch barrier counters
__device__ unsigned int  g_done;                               // last-CTA-out counter

// Packed fp32x2 FMA.
__device__ __forceinline__ void ffma2(float2& d, const float2 a, const float2 b) {
    unsigned long long da = *(const unsigned long long*)&a;
    unsigned long long db = *(const unsigned long long*)&b;
    unsigned long long dd = *(unsigned long long*)&d;
    asm("fma.rn.f32x2 %0, %1, %2, %3;" : "=l"(dd) : "l"(da), "l"(db), "l"(dd));
    d = *(float2*)&dd;
}

__device__ __forceinline__ float2 h2lo(unsigned int h) {
    return __half22float2(*(const __half2*)&h);
}
__device__ __forceinline__ unsigned int f22h2(float x, float y) {
    __half2 h = __floats2half2_rn(x, y);
    return *(unsigned int*)&h;
}

// Row core: dot(G_row, v) -> warp-reduce -> u -> colacc += u * G_row.
__device__ __forceinline__ void row_core(const float2 gf[8],
                                         const float2* __restrict__ vreg,
                                         float2* __restrict__ colacc,
                                         float mu_r, float* uout, int lane) {
    float2 acc = make_float2(0.f, 0.f);
#pragma unroll
    for (int k = 0; k < 8; k++) ffma2(acc, gf[k], vreg[k]);
    float s = acc.x + acc.y;
#pragma unroll
    for (int off = 16; off; off >>= 1)
        s += __shfl_xor_sync(0xffffffffu, s, off);
    float u = __fdividef(mu_r, s);
    if (lane == 0) *uout = u;          // consumed by sink_final
    float2 u2 = make_float2(u, u);
#pragma unroll
    for (int k = 0; k < 8; k++) ffma2(colacc[k], gf[k], u2);
}

// ---------------------------------------------------------------------------
// Persistent Sinkhorn kernel:
//   iter 0    : G = exp(-C/eps) fp16 generated inline (v0 = 1/m const), C read
//               exactly once via __ldcg.
//   iters 1+  : one fp16-G pass/iter, 4-row load batching, first RESROWS rows
//               L1-resident (no fences anywhere -> L1 never flushed).
//   exit      : deterministic per-batch convergence test on v.
//   tail      : persist v; last CTA out resets barrier state for next replay.
// ---------------------------------------------------------------------------
__global__ void __launch_bounds__(TPB, 1)
sink_iter(const float* __restrict__ C, const float* __restrict__ mu,
          const float* __restrict__ nu) {
    const int cta  = blockIdx.x;
    const int b    = cta / CPB;
    const int r    = cta % CPB;
    const int tid  = threadIdx.x;
    const int lane = tid & 31;
    const int w    = tid >> 5;

    __shared__ __align__(16) float sv[MCOL];            // v for this batch
    __shared__ float smu[ROWS_PER_CTA];                 // mu slice for this CTA
    __shared__ __align__(16) float swred[NSLOT][MCOL];  // folded warp partials (16KB)
    __shared__ float sdel[RELT / 32];                   // per-warp max |dv|/v
    __shared__ int   sbrk;

    const int rowbase = r * ROWS_PER_CTA;
    for (int j = tid; j < MCOL; j += TPB) sv[j] = 1.0f / MCOL;
    for (int j = tid; j < ROWS_PER_CTA; j += TPB) smu[j] = mu[rowbase + j];
    if (tid == 0) sbrk = 0;
    __syncthreads();

    const int i0 = rowbase + w * ROWS_PER_WARP;
    uint4*        Gw  = (uint4*)(g_G + ((size_t)b * NROW + i0) * (MCOL / 2));
    const float*  Cw  = C + ((size_t)b * NROW + i0) * MCOL;
    float*        uw  = g_u + b * NROW + i0;
    const float2* sv2 = (const float2*)sv;
    unsigned int* bar = &g_bar[b];
    const int h0 = 4 * lane;          // half2 group 1: cols 8l..8l+7
    const int h1 = 128 + 4 * lane;    // half2 group 2: cols 256+8l..+7

    for (int t = 0; t < ITERS; t++) {
        float2 vreg[8];
#pragma unroll
        for (int k = 0; k < 4; k++) { vreg[k] = sv2[h0 + k]; vreg[4 + k] = sv2[h1 + k]; }

        float2 colacc[8];
#pragma unroll
        for (int k = 0; k < 8; k++) colacc[k] = make_float2(0.f, 0.f);

        if (t == 0) {
            // Fused init: C -> G fp16 (written once) + iteration 0 on the
            // quantized values. __ldcg keeps C out of L1 (reserved for G).
#pragma unroll 2
            for (int rr = 0; rr < ROWS_PER_WARP; rr++) {
                const float4* cp = (const float4*)(Cw + (size_t)rr * MCOL);
                float4 a0 = __ldcg(cp + 2 * lane),      a1 = __ldcg(cp + 2 * lane + 1);
                float4 b0 = __ldcg(cp + 64 + 2 * lane), b1 = __ldcg(cp + 64 + 2 * lane + 1);
                uint4 q0, q1;
                q0.x = f22h2(__expf(-a0.x * INV_EPS), __expf(-a0.y * INV_EPS));
                q0.y = f22h2(__expf(-a0.z * INV_EPS), __expf(-a0.w * INV_EPS));
                q0.z = f22h2(__expf(-a1.x * INV_EPS), __expf(-a1.y * INV_EPS));
                q0.w = f22h2(__expf(-a1.z * INV_EPS), __expf(-a1.w * INV_EPS));
                q1.x = f22h2(__expf(-b0.x * INV_EPS), __expf(-b0.y * INV_EPS));
                q1.y = f22h2(__expf(-b0.z * INV_EPS), __expf(-b0.w * INV_EPS));
                q1.z = f22h2(__expf(-b1.x * INV_EPS), __expf(-b1.y * INV_EPS));
                q1.w = f22h2(__expf(-b1.z * INV_EPS), __expf(-b1.w * INV_EPS));
                uint4* rp = Gw + rr * (MCOL / 8);
                rp[lane]      = q0;
                rp[32 + lane] = q1;
                float2 gf[8];
                gf[0] = h2lo(q0.x); gf[1] = h2lo(q0.y); gf[2] = h2lo(q0.z); gf[3] = h2lo(q0.w);
                gf[4] = h2lo(q1.x); gf[5] = h2lo(q1.y); gf[6] = h2lo(q1.z); gf[7] = h2lo(q1.w);
                row_core(gf, vreg, colacc, smu[w * ROWS_PER_WARP + rr], uw + rr, lane);
            }
        } else {
#pragma unroll
            for (int chunk = 0; chunk < ROWS_PER_WARP / 4; chunk++) {
                uint4 Pq[4][2];
#pragma unroll
                for (int q = 0; q < 4; q++) {
                    const int rr = chunk * 4 + q;
                    const uint4* rp = Gw + rr * (MCOL / 8);
                    if (rr < RESROWS) {                 // L1-resident subset
                        Pq[q][0] = rp[lane];
                        Pq[q][1] = rp[32 + lane];
                    } else {                            // streaming: L2 only
                        Pq[q][0] = __ldcg(rp + lane);
                        Pq[q][1] = __ldcg(rp + 32 + lane);
                    }
                }
#pragma unroll
                for (int q = 0; q < 4; q++) {
                    const int rr = chunk * 4 + q;
                    float2 gf[8];
                    gf[0] = h2lo(Pq[q][0].x); gf[1] = h2lo(Pq[q][0].y);
                    gf[2] = h2lo(Pq[q][0].z); gf[3] = h2lo(Pq[q][0].w);
                    gf[4] = h2lo(Pq[q][1].x); gf[5] = h2lo(Pq[q][1].y);
                    gf[6] = h2lo(Pq[q][1].z); gf[7] = h2lo(Pq[q][1].w);
                    row_core(gf, vreg, colacc, smu[w * ROWS_PER_WARP + rr], uw + rr, lane);
                }
            }
        }

        // Phase 1: warps 0-7 store partials (STS.128, no atomics).
        if (w < NSLOT) {
            float4* d0 = (float4*)&swred[w][2 * h0];
            d0[0] = make_float4(colacc[0].x, colacc[0].y, colacc[1].x, colacc[1].y);
            d0[1] = make_float4(colacc[2].x, colacc[2].y, colacc[3].x, colacc[3].y);
            float4* d1 = (float4*)&swred[w][2 * h1];
            d1[0] = make_float4(colacc[4].x, colacc[4].y, colacc[5].x, colacc[5].y);
            d1[1] = make_float4(colacc[6].x, colacc[6].y, colacc[7].x, colacc[7].y);
        }
        __syncthreads();
        // Phase 2: warps 8-15 fold into slot w-8 (lane-disjoint RMW).
        if (w >= NSLOT) {
            const int ws = w - NSLOT;
            float4* d0 = (float4*)&swred[ws][2 * h0];
            float4 a0 = d0[0], a1 = d0[1];
            d0[0] = make_float4(a0.x + colacc[0].x, a0.y + colacc[0].y,
                                a0.z + colacc[1].x, a0.w + colacc[1].y);
            d0[1] = make_float4(a1.x + colacc[2].x, a1.y + colacc[2].y,
                                a1.z + colacc[3].x, a1.w + colacc[3].y);
            float4* d1 = (float4*)&swred[ws][2 * h1];
            float4 b0 = d1[0], b1 = d1[1];
            d1[0] = make_float4(b0.x + colacc[4].x, b0.y + colacc[4].y,
                                b0.z + colacc[5].x, b0.w + colacc[5].y);
            d1[1] = make_float4(b1.x + colacc[6].x, b1.y + colacc[6].y,
                                b1.z + colacc[7].x, b1.w + colacc[7].y);
        }
        __syncthreads();

        const int p = t & 1;
        if (tid < RELT) {
            float4 s = make_float4(0.f, 0.f, 0.f, 0.f);
#pragma unroll
            for (int w2 = 0; w2 < NSLOT; w2++) {
                float4 a = *(const float4*)&swred[w2][4 * tid];
                s.x += a.x; s.y += a.y; s.z += a.z; s.w += a.w;
            }
            ((float4*)&g_part[p][b][r][0])[tid] = s;
            // Release by the SAME thread that stored -> no membar/L1-flush.
            asm volatile("red.release.gpu.global.add.u32 [%0], %1;"
                         :: "l"(bar), "r"(1u) : "memory");
        }
        if (tid == 0) {
            const unsigned int target = (unsigned)(RELT * CPB) * (unsigned)(t + 1);
            unsigned int c;
            do {
                asm volatile("ld.acquire.gpu.global.u32 %0, [%1];"
                             : "=r"(c) : "l"(bar) : "memory");
                if (c >= target) break;
                __nanosleep(32);
            } while (true);
        }
        __syncthreads();

        // v update + convergence metric (bit-identical in all 4 CTAs).
        if (tid < RELT) {
            float4 cs = __ldcg((const float4*)&g_part[p][b][0][4 * tid]);
            float4 c1 = __ldcg((const float4*)&g_part[p][b][1][4 * tid]);
            float4 c2 = __ldcg((const float4*)&g_part[p][b][2][4 * tid]);
            float4 c3 = __ldcg((const float4*)&g_part[p][b][3][4 * tid]);
            cs.x += c1.x + c2.x + c3.x;  cs.y += c1.y + c2.y + c3.y;
            cs.z += c1.z + c2.z + c3.z;  cs.w += c1.w + c2.w + c3.w;
            float4 nu4 = __ldg((const float4*)&nu[4 * tid]);
            float4 vv;
            vv.x = nu4.x / cs.x;  vv.y = nu4.y / cs.y;
            vv.z = nu4.z / cs.z;  vv.w = nu4.w / cs.w;
            float4 old = ((float4*)sv)[tid];
            ((float4*)sv)[tid] = vv;
            float d = fmaxf(fmaxf(fabsf(vv.x - old.x) / vv.x,
                                  fabsf(vv.y - old.y) / vv.y),
                            fmaxf(fabsf(vv.z - old.z) / vv.z,
                                  fabsf(vv.w - old.w) / vv.w));
#pragma unroll
            for (int off = 16; off; off >>= 1)
                d = fmaxf(d, __shfl_xor_sync(0xffffffffu, d, off));
            if (lane == 0) sdel[w] = d;
        }
        __syncthreads();
        if (tid == 0) {
            float dm = fmaxf(fmaxf(sdel[0], sdel[1]), fmaxf(sdel[2], sdel[3]));
            sbrk = (t >= 2 && dm < CONV_TOL) ? 1 : 0;
        }
        __syncthreads();
        if (sbrk) break;    // identical decision in all CTAs of this batch
    }

    // Persist final v for sink_final (one CTA per batch).
    if (r == 0)
        for (int j = tid; j < MCOL; j += TPB) g_v[b * MCOL + j] = sv[j];

    // ---- Last CTA out resets barrier state for the next graph replay ----
    __syncthreads();
    if (tid == 0) {
        unsigned int old = atomicAdd(&g_done, 1u);
        if (old == (unsigned)gridDim.x - 1u) {      // every other CTA fully done
#pragma unroll
            for (int i = 0; i < BS; i++) g_bar[i] = 0u;
            g_done = 0u;
        }
    }
}

// ---------------------------------------------------------------------------
// Final (wide grid): P = u * G * v with G fp16 read from L2 (64 MB, hot).
// One uint4 of G (8 elements) per thread; HBM-write-bound.
// 16384 x 256 threads == BS*NROW*MCOL/8 exactly.
// ---------------------------------------------------------------------------
__global__ void sink_final(float* __restrict__ P) {
    const size_t t = (size_t)blockIdx.x * blockDim.x + threadIdx.x;   // uint4 idx
    const uint4 q = __ldcg((const uint4*)g_G + t);
    const int j8  = (int)(t & (MCOL / 8 - 1)) * 8;    // column of first element
    const int row = (int)(t >> 6);                    // b*NROW + i
    const int b   = row >> 11;
    const float u = g_u[row];
    const float4* vb = (const float4*)(g_v + b * MCOL + j8);
    const float4 v0 = vb[0], v1 = vb[1];
    const float2 g0 = h2lo(q.x), g1 = h2lo(q.y), g2 = h2lo(q.z), g3 = h2lo(q.w);
    float4* dst = (float4*)(P + (size_t)row * MCOL + j8);
    dst[0] = make_float4(u * g0.x * v0.x, u * g0.y * v0.y,
                         u * g1.x * v0.z, u * g1.y * v0.w);
    dst[1] = make_float4(u * g2.x * v1.x, u * g2.y * v1.y,
                         u * g3.x * v1.z, u * g3.y * v1.w);
}

// ---------------------------------------------------------------------------
extern "C" void kernel_launch(void* const* d_in, const int* in_sizes, int n_in,
                              void* d_out, int out_size) {
    const float* C  = (const float*)d_in[0];
    const float* mu = (const float*)d_in[1];
    const float* nu = (const float*)d_in[2];
    float*       P  = (float*)d_out;

    sink_iter<<<BS * CPB, TPB>>>(C, mu, nu);
    sink_final<<<16384, 256>>>(P);
}